// round 4
// baseline (speedup 1.0000x reference)
#include <cuda_runtime.h>

// Problem constants (shapes are fixed by the dataset)
#define NN     100000
#define NFEAT  512
#define NHID   64
#define NCLS   16
#define NE_MAX 3200000

#define SCAN_T     256
#define SCAN_ELEMS 2048   // 256 threads * 8 elems

// ---------------- device scratch (no allocations allowed) ----------------
__device__ int   g_cnt[NN];
__device__ float g_dis[NN];
__device__ int   g_ptr[NN + 1];
__device__ int   g_cur[NN];
__device__ int   g_src[NE_MAX];
__device__ float g_wgt[NE_MAX];
__device__ float g_h0[NN * NCLS];
__device__ float g_bufA[NN * NCLS];
__device__ float g_bufB[NN * NCLS];
__device__ float g_w1t[NFEAT * NHID];   // W1 transposed: [k][hid]
__device__ int   g_bsum[256];
__device__ int   g_is64;                // edge_index element width flag

// ---------------- f32x2 helpers (packed FFMA2: 2 MACs/instr) ----------------
__device__ __forceinline__ unsigned long long pack2(float lo, float hi) {
    unsigned long long r;
    asm("mov.b64 %0, {%1, %2};" : "=l"(r) : "f"(lo), "f"(hi));
    return r;
}
__device__ __forceinline__ void unpack2(unsigned long long v, float& lo, float& hi) {
    asm("mov.b64 {%0, %1}, %2;" : "=f"(lo), "=f"(hi) : "l"(v));
}
__device__ __forceinline__ unsigned long long ffma2(unsigned long long a,
                                                    unsigned long long b,
                                                    unsigned long long c) {
    unsigned long long d;
    asm("fma.rn.f32x2 %0, %1, %2, %3;" : "=l"(d) : "l"(a), "l"(b), "l"(c));
    return d;
}

// ---------------- edge dtype detection ----------------
// If edge_index is int64 (values in [0, NN)), every odd int32 word of the
// buffer (the high halves) is 0. If it is int32, those words are random node
// indices — P(2048 consecutive are all zero) ~ 0. One block, deterministic.
__global__ void k_detect(const int* __restrict__ ei32, int E) {
    __shared__ int nz;
    if (threadIdx.x == 0) nz = 0;
    __syncthreads();
    int lim = (E < 2048) ? E : 2048;
    int cnt = 0;
    for (int i = threadIdx.x; i < lim; i += blockDim.x)
        if (ei32[2 * i + 1] != 0) cnt++;
    atomicAdd(&nz, cnt);
    __syncthreads();
    if (threadIdx.x == 0) g_is64 = (nz == 0) ? 1 : 0;
}

__device__ __forceinline__ int edge_at(const void* ei, size_t pos) {
    if (g_is64) return (int)((const long long*)ei)[pos];
    return ((const int*)ei)[pos];
}

// ---------------- small utility kernels ----------------
__global__ void k_init(int n) {
    int i = blockIdx.x * blockDim.x + threadIdx.x;
    if (i < n) g_cnt[i] = 0;
}

__global__ void k_wt(const float* __restrict__ W1) {
    int idx = blockIdx.x * blockDim.x + threadIdx.x;
    if (idx < NFEAT * NHID) {
        int j = idx / NFEAT;   // hid
        int k = idx % NFEAT;   // feat (coalesced read)
        g_w1t[k * NHID + j] = W1[idx];
    }
}

__global__ void k_count(const void* __restrict__ ei, int E) {
    int idx = blockIdx.x * blockDim.x + threadIdx.x;
    if (idx < E) {
        int c = edge_at(ei, (size_t)E + idx);
        if ((unsigned)c < NN) atomicAdd(&g_cnt[c], 1);
    }
}

__global__ void k_dis(int n) {
    int i = blockIdx.x * blockDim.x + threadIdx.x;
    if (i < n) g_dis[i] = rsqrtf((float)(g_cnt[i] + 1));   // +1 self-loop
}

// ---------------- exclusive scan of g_cnt -> g_ptr (3 kernels) ----------------
__global__ void k_scan1(int n) {
    __shared__ int sred[SCAN_T];
    int b = blockIdx.x, t = threadIdx.x;
    int base = b * SCAN_ELEMS + t * 8;
    int s = 0;
#pragma unroll
    for (int i = 0; i < 8; ++i) {
        int idx = base + i;
        if (idx < n) s += g_cnt[idx];
    }
    sred[t] = s;
    __syncthreads();
    for (int off = SCAN_T / 2; off >= 1; off >>= 1) {
        if (t < off) sred[t] += sred[t + off];
        __syncthreads();
    }
    if (t == 0) g_bsum[b] = sred[0];
}

__global__ void k_scan2(int nblk, int n) {
    if (threadIdx.x == 0 && blockIdx.x == 0) {
        int run = 0;
        for (int b = 0; b < nblk; ++b) {
            int v = g_bsum[b];
            g_bsum[b] = run;
            run += v;
        }
        g_ptr[n] = run;   // == E (of in-range edges)
    }
}

__global__ void k_scan3(int n) {
    __shared__ int ss[SCAN_T];
    int b = blockIdx.x, t = threadIdx.x;
    int base = b * SCAN_ELEMS + t * 8;
    int v[8];
    int tot = 0;
#pragma unroll
    for (int i = 0; i < 8; ++i) {
        int idx = base + i;
        v[i] = (idx < n) ? g_cnt[idx] : 0;
        tot += v[i];
    }
    ss[t] = tot;
    __syncthreads();
    // Hillis-Steele inclusive scan over thread totals
    for (int off = 1; off < SCAN_T; off <<= 1) {
        int a = (t >= off) ? ss[t - off] : 0;
        __syncthreads();
        ss[t] += a;
        __syncthreads();
    }
    int run = g_bsum[b] + ss[t] - tot;   // exclusive offset for this thread
#pragma unroll
    for (int i = 0; i < 8; ++i) {
        int idx = base + i;
        if (idx < n) {
            g_ptr[idx] = run;
            g_cur[idx] = run;
            run += v[i];
        }
    }
}

__global__ void k_fill(const void* __restrict__ ei, int E) {
    int idx = blockIdx.x * blockDim.x + threadIdx.x;
    if (idx < E) {
        int r = edge_at(ei, idx);
        int c = edge_at(ei, (size_t)E + idx);
        if ((unsigned)r < NN && (unsigned)c < NN) {
            int pos = atomicAdd(&g_cur[c], 1);
            g_src[pos] = r;
            g_wgt[pos] = g_dis[r] * g_dis[c];
        }
    }
}

// ---------------- fused MLP: h0 = relu(x@W1^T+b1)@W2^T + b2 ----------------
// Block: 128 threads, tile TM=128 nodes x TN=64 hid, TK=16, 8x8 micro-tile
// using packed fma.rn.f32x2 (2 MACs/instr). GEMM2 fused via SMEM staging.
__global__ __launch_bounds__(128) void k_gemm(const float* __restrict__ x,
                                              const float* __restrict__ b1,
                                              const float* __restrict__ W2,
                                              const float* __restrict__ b2,
                                              int n) {
    __shared__ __align__(16) float sm[9360];   // 37.4 KB
    float* Xs = sm;          // [16][128]  (phase 1)
    float* Ws = sm + 2048;   // [16][64]   (phase 1)

    const int t = threadIdx.x;
    const int nodeBase = blockIdx.x * 128;
    const int ty = t >> 3;   // 0..15  -> rows ty*8..ty*8+7
    const int tx = t & 7;    // 0..7   -> cols tx*8..tx*8+7

    unsigned long long acc2[8][4];
#pragma unroll
    for (int i = 0; i < 8; ++i)
#pragma unroll
        for (int j = 0; j < 4; ++j) acc2[i][j] = 0ull;

    for (int kt = 0; kt < NFEAT / 16; ++kt) {
        // load X tile: 128 nodes x 16 k (float4 per slot)
#pragma unroll
        for (int i = 0; i < 4; ++i) {
            int slot = t + i * 128;      // 0..511
            int node = slot >> 2;
            int kq = slot & 3;
            int gn = nodeBase + node;
            float4 v = make_float4(0.f, 0.f, 0.f, 0.f);
            if (gn < n)
                v = *reinterpret_cast<const float4*>(x + (size_t)gn * NFEAT + kt * 16 + kq * 4);
            Xs[(kq * 4 + 0) * 128 + node] = v.x;
            Xs[(kq * 4 + 1) * 128 + node] = v.y;
            Xs[(kq * 4 + 2) * 128 + node] = v.z;
            Xs[(kq * 4 + 3) * 128 + node] = v.w;
        }
        // load W tile from transposed W1 (coalesced)
#pragma unroll
        for (int i = 0; i < 2; ++i) {
            int slot = t + i * 128;      // 0..255
            int k = slot >> 4;
            int cq = slot & 15;
            float4 v = *reinterpret_cast<const float4*>(g_w1t + (kt * 16 + k) * 64 + cq * 4);
            *reinterpret_cast<float4*>(Ws + k * 64 + cq * 4) = v;
        }
        __syncthreads();
#pragma unroll
        for (int k = 0; k < 16; ++k) {
            float4 xa = *reinterpret_cast<const float4*>(Xs + k * 128 + ty * 8);
            float4 xb = *reinterpret_cast<const float4*>(Xs + k * 128 + ty * 8 + 4);
            ulonglong2 wa = *reinterpret_cast<const ulonglong2*>(Ws + k * 64 + tx * 8);
            ulonglong2 wb = *reinterpret_cast<const ulonglong2*>(Ws + k * 64 + tx * 8 + 4);
            unsigned long long w4[4] = {wa.x, wa.y, wb.x, wb.y};
            float xr[8] = {xa.x, xa.y, xa.z, xa.w, xb.x, xb.y, xb.z, xb.w};
#pragma unroll
            for (int r = 0; r < 8; ++r) {
                unsigned long long ar = pack2(xr[r], xr[r]);
#pragma unroll
                for (int c = 0; c < 4; ++c)
                    acc2[r][c] = ffma2(ar, w4[c], acc2[r][c]);
            }
        }
        __syncthreads();
    }

    // ---- phase 2: relu+bias -> SMEM, then h0 = Hs @ W2^T + b2 ----
    float* Hs = sm;            // [128][65] padded (aliases Xs/Ws, safe post-sync)
    float* W2s = sm + 8320;    // [16][65] padded
    float bb[8];
#pragma unroll
    for (int j = 0; j < 8; ++j) bb[j] = b1[tx * 8 + j];
#pragma unroll
    for (int i = 0; i < 8; ++i) {
        int row = ty * 8 + i;
#pragma unroll
        for (int c = 0; c < 4; ++c) {
            float lo, hi;
            unpack2(acc2[i][c], lo, hi);
            Hs[row * 65 + tx * 8 + c * 2]     = fmaxf(lo + bb[c * 2], 0.f);
            Hs[row * 65 + tx * 8 + c * 2 + 1] = fmaxf(hi + bb[c * 2 + 1], 0.f);
        }
    }
    for (int idx = t; idx < NCLS * NHID; idx += 128) {
        int c = idx >> 6, k = idx & 63;
        W2s[c * 65 + k] = W2[idx];
    }
    __syncthreads();

    int c = t & 15;            // class
    int ng = t >> 4;           // 0..7
    float bc = b2[c];
#pragma unroll
    for (int i = 0; i < 16; ++i) {
        int nrow = ng * 16 + i;
        int gn = nodeBase + nrow;
        float acc = bc;
#pragma unroll
        for (int k = 0; k < 64; ++k)
            acc += Hs[nrow * 65 + k] * W2s[c * 65 + k];
        if (gn < n) g_h0[gn * NCLS + c] = acc;
    }
}

// ---------------- one APPNP propagation step (atomic-free via CSR) ----------
// 16 lanes per node (one per class). Edges read cooperatively, broadcast
// via width-16 shfl; h gathers hit L2 (buffers are 6.4 MB, L2-resident).
__global__ __launch_bounds__(128) void k_prop(int srcSel, int dstSel, int n) {
    int t = blockIdx.x * blockDim.x + threadIdx.x;
    int node = t >> 4;
    if (node >= n) return;
    int lane = t & 15;
    const float* __restrict__ hin =
        (srcSel == 0) ? g_h0 : ((srcSel == 1) ? g_bufA : g_bufB);
    float* __restrict__ hout = (dstSel == 1) ? g_bufA : g_bufB;

    unsigned gmask = 0xFFFFu << (threadIdx.x & 0x10);
    int start = g_ptr[node], end = g_ptr[node + 1];
    float acc = 0.f;
    for (int base = start; base < end; base += 16) {
        int e = base + lane;
        int s = (e < end) ? g_src[e] : -1;
        float wv = (e < end) ? g_wgt[e] : 0.f;
#pragma unroll
        for (int j = 0; j < 16; ++j) {
            int sj = __shfl_sync(gmask, s, j, 16);
            float wj = __shfl_sync(gmask, wv, j, 16);
            if (sj >= 0) acc += wj * __ldg(hin + sj * 16 + lane);
        }
    }
    float dv = g_dis[node];                       // self-loop: norm = dis^2
    acc += dv * dv * hin[node * 16 + lane];
    hout[node * 16 + lane] = 0.9f * acc + 0.1f * g_h0[node * 16 + lane];
}

__global__ __launch_bounds__(128) void k_logsoftmax(float* __restrict__ out, int n) {
    int t = blockIdx.x * blockDim.x + threadIdx.x;
    int node = t >> 4;
    if (node >= n) return;
    int lane = t & 15;
    unsigned gmask = 0xFFFFu << (threadIdx.x & 0x10);
    float v = g_bufB[node * 16 + lane];
    float m = v;
#pragma unroll
    for (int off = 8; off >= 1; off >>= 1)
        m = fmaxf(m, __shfl_xor_sync(gmask, m, off, 16));
    float e = expf(v - m);
    float s = e;
#pragma unroll
    for (int off = 8; off >= 1; off >>= 1)
        s += __shfl_xor_sync(gmask, s, off, 16);
    out[node * 16 + lane] = v - m - logf(s);
}

// ---------------- launch ----------------
extern "C" void kernel_launch(void* const* d_in, const int* in_sizes, int n_in,
                              void* d_out, int out_size) {
    const float* x  = (const float*)d_in[0];
    const float* W1 = (const float*)d_in[1];
    const float* b1 = (const float*)d_in[2];
    const float* W2 = (const float*)d_in[3];
    const float* b2 = (const float*)d_in[4];
    const void*  ei = d_in[5];
    float* out = (float*)d_out;

    int N = in_sizes[0] / NFEAT;
    int E = in_sizes[5] / 2;
    int sblocks = (N + SCAN_ELEMS - 1) / SCAN_ELEMS;

    // edge dtype detection + degree + normalization + CSR build
    k_detect<<<1, 256>>>((const int*)ei, E);
    k_init<<<(N + 255) / 256, 256>>>(N);
    k_wt<<<(NFEAT * NHID + 255) / 256, 256>>>(W1);
    k_count<<<(E + 255) / 256, 256>>>(ei, E);
    k_dis<<<(N + 255) / 256, 256>>>(N);
    k_scan1<<<sblocks, SCAN_T>>>(N);
    k_scan2<<<1, 32>>>(sblocks, N);
    k_scan3<<<sblocks, SCAN_T>>>(N);
    k_fill<<<(E + 255) / 256, 256>>>(ei, E);

    // fused MLP -> g_h0
    k_gemm<<<(N + 127) / 128, 128>>>(x, b1, W2, b2, N);

    // K=10 APPNP steps, ping-pong: h0 -> A -> B -> A ... -> B
    int grid = (N * 16 + 127) / 128;
    int src = 0;
    for (int step = 1; step <= 10; ++step) {
        int dst = (step & 1) ? 1 : 2;
        k_prop<<<grid, 128>>>(src, dst, N);
        src = dst;
    }
    k_logsoftmax<<<grid, 128>>>(out, N);
}

// round 6
// speedup vs baseline: 1.6992x; 1.6992x over previous
#include <cuda_runtime.h>
#include <cuda_fp16.h>
#include <cstdint>

// Problem constants
#define NN     100000
#define NFEAT  512
#define NHID   64
#define NCLS   16
#define NE_MAX 3200000

#define SCAN_T     256
#define SCAN_ELEMS 2048

// ---------------- device scratch ----------------
__device__ int    g_cnt[NN];
__device__ float  g_dis[NN];
__device__ int    g_ptr[NN + 1];
__device__ int    g_cur[NN];
__device__ int2   g_edge[NE_MAX];          // {src, weight_bits}
__device__ __half g_h0h[NN * NCLS];
__device__ __half g_bufA[NN * NCLS];
__device__ __half g_bufB[NN * NCLS];
__device__ int    g_bsum[256];
__device__ int    g_is64;

__device__ __forceinline__ uint32_t h2u(__half2 h) { return *reinterpret_cast<uint32_t*>(&h); }

// ---------------- edge dtype detection ----------------
__global__ void k_detect(const int* __restrict__ ei32, int E) {
    __shared__ int nz;
    if (threadIdx.x == 0) nz = 0;
    __syncthreads();
    int lim = (E < 2048) ? E : 2048;
    int cnt = 0;
    for (int i = threadIdx.x; i < lim; i += blockDim.x)
        if (ei32[2 * i + 1] != 0) cnt++;
    atomicAdd(&nz, cnt);
    __syncthreads();
    if (threadIdx.x == 0) g_is64 = (nz == 0) ? 1 : 0;
}
__device__ __forceinline__ int edge_at(const void* ei, size_t pos) {
    if (g_is64) return (int)((const long long*)ei)[pos];
    return ((const int*)ei)[pos];
}

// ---------------- CSR build ----------------
__global__ void k_init(int n) {
    int i = blockIdx.x * blockDim.x + threadIdx.x;
    if (i < n) g_cnt[i] = 0;
}
__global__ void k_count(const void* __restrict__ ei, int E) {
    int idx = blockIdx.x * blockDim.x + threadIdx.x;
    if (idx < E) {
        int c = edge_at(ei, (size_t)E + idx);
        if ((unsigned)c < NN) atomicAdd(&g_cnt[c], 1);
    }
}
__global__ void k_dis(int n) {
    int i = blockIdx.x * blockDim.x + threadIdx.x;
    if (i < n) g_dis[i] = rsqrtf((float)(g_cnt[i] + 1));
}
__global__ void k_scan1(int n) {
    __shared__ int sred[SCAN_T];
    int b = blockIdx.x, t = threadIdx.x;
    int base = b * SCAN_ELEMS + t * 8;
    int s = 0;
#pragma unroll
    for (int i = 0; i < 8; ++i) {
        int idx = base + i;
        if (idx < n) s += g_cnt[idx];
    }
    sred[t] = s;
    __syncthreads();
    for (int off = SCAN_T / 2; off >= 1; off >>= 1) {
        if (t < off) sred[t] += sred[t + off];
        __syncthreads();
    }
    if (t == 0) g_bsum[b] = sred[0];
}
__global__ void k_scan2(int nblk, int n) {
    if (threadIdx.x == 0 && blockIdx.x == 0) {
        int run = 0;
        for (int b = 0; b < nblk; ++b) {
            int v = g_bsum[b];
            g_bsum[b] = run;
            run += v;
        }
        g_ptr[n] = run;
    }
}
__global__ void k_scan3(int n) {
    __shared__ int ss[SCAN_T];
    int b = blockIdx.x, t = threadIdx.x;
    int base = b * SCAN_ELEMS + t * 8;
    int v[8];
    int tot = 0;
#pragma unroll
    for (int i = 0; i < 8; ++i) {
        int idx = base + i;
        v[i] = (idx < n) ? g_cnt[idx] : 0;
        tot += v[i];
    }
    ss[t] = tot;
    __syncthreads();
    for (int off = 1; off < SCAN_T; off <<= 1) {
        int a = (t >= off) ? ss[t - off] : 0;
        __syncthreads();
        ss[t] += a;
        __syncthreads();
    }
    int run = g_bsum[b] + ss[t] - tot;
#pragma unroll
    for (int i = 0; i < 8; ++i) {
        int idx = base + i;
        if (idx < n) {
            g_ptr[idx] = run;
            g_cur[idx] = run;
            run += v[i];
        }
    }
}
__global__ void k_fill(const void* __restrict__ ei, int E) {
    int idx = blockIdx.x * blockDim.x + threadIdx.x;
    if (idx < E) {
        int r = edge_at(ei, idx);
        int c = edge_at(ei, (size_t)E + idx);
        if ((unsigned)r < NN && (unsigned)c < NN) {
            int pos = atomicAdd(&g_cur[c], 1);
            g_edge[pos] = make_int2(r, __float_as_int(g_dis[r] * g_dis[c]));
        }
    }
}

// ---------------- fused MLP via mma.sync (HMMA, portable sm_80+) -------------
// CTA: 256 thr = 8 warps (4 M x 2 N). Tile: 128 nodes x 64 hid, K chunk 64.
// A/B fp32->fp16 into padded SMEM (stride 72 halfs = 36 u32 -> conflict-free
// (4r+q) fragment banks). W1 [hid][feat] row-major == col-major KxN operand.
#define TM 128
#define TKC 64
#define NCHUNK (NFEAT / TKC)
#define LDA 72          // halfs per row (36 u32)
#define LDW2 65         // floats per class row

#define SMO_W2 0                          // 16*65*4 = 4160 B
#define SMO_A  4160                       // 128*72*2 = 18432 B
#define SMO_B  22592                      // 64*72*2  =  9216 B
#define SM_TOTAL 31808

__device__ __forceinline__ void mma16816(float* d, uint32_t a0, uint32_t a1,
                                         uint32_t a2, uint32_t a3,
                                         uint32_t b0, uint32_t b1) {
    asm volatile(
        "mma.sync.aligned.m16n8k16.row.col.f32.f16.f16.f32 "
        "{%0,%1,%2,%3}, {%4,%5,%6,%7}, {%8,%9}, {%0,%1,%2,%3};"
        : "+f"(d[0]), "+f"(d[1]), "+f"(d[2]), "+f"(d[3])
        : "r"(a0), "r"(a1), "r"(a2), "r"(a3), "r"(b0), "r"(b1));
}

__global__ __launch_bounds__(256) void k_gemm(const float* __restrict__ x,
                                              const float* __restrict__ W1,
                                              const float* __restrict__ b1,
                                              const float* __restrict__ W2,
                                              const float* __restrict__ b2,
                                              int n) {
    __shared__ __align__(16) unsigned char sm[SM_TOTAL];
    float*    W2s  = (float*)(sm + SMO_W2);
    uint32_t* As32 = (uint32_t*)(sm + SMO_A);
    uint32_t* Bs32 = (uint32_t*)(sm + SMO_B);

    const int t = threadIdx.x, wid = t >> 5, lane = t & 31;
    const int warpM = wid & 3, warpN = wid >> 2;     // 4 x 2
    const int r = lane >> 2, q = lane & 3;
    const int nodeBase = blockIdx.x * TM;

    for (int i = t; i < NCLS * NHID; i += 256)
        W2s[(i >> 6) * LDW2 + (i & 63)] = W2[i];

    float acc[2][4][4];
#pragma unroll
    for (int mt = 0; mt < 2; ++mt)
#pragma unroll
        for (int nt = 0; nt < 4; ++nt)
#pragma unroll
            for (int j = 0; j < 4; ++j) acc[mt][nt][j] = 0.f;

    for (int c = 0; c < NCHUNK; ++c) {
        // A: 128 rows x 64 halfs; 1024 slots of 8 halfs, 4 iters
#pragma unroll
        for (int i = 0; i < 4; ++i) {
            int slot = t + i * 256;
            int row = slot >> 3, g = slot & 7;
            int gn = nodeBase + row;
            float4 va = make_float4(0.f, 0.f, 0.f, 0.f), vb = va;
            if (gn < n) {
                const float* p = x + (size_t)gn * NFEAT + c * TKC + g * 8;
                va = *(const float4*)p;
                vb = *(const float4*)(p + 4);
            }
            uint4 u;
            u.x = h2u(__floats2half2_rn(va.x, va.y));
            u.y = h2u(__floats2half2_rn(va.z, va.w));
            u.z = h2u(__floats2half2_rn(vb.x, vb.y));
            u.w = h2u(__floats2half2_rn(vb.z, vb.w));
            *(uint4*)(As32 + row * (LDA / 2) + g * 4) = u;
        }
        // B (W1 chunk): 64 rows x 64 halfs; 512 slots, 2 iters
#pragma unroll
        for (int i = 0; i < 2; ++i) {
            int slot = t + i * 256;
            int row = slot >> 3, g = slot & 7;
            const float* p = W1 + (size_t)row * NFEAT + c * TKC + g * 8;
            float4 va = *(const float4*)p;
            float4 vb = *(const float4*)(p + 4);
            uint4 u;
            u.x = h2u(__floats2half2_rn(va.x, va.y));
            u.y = h2u(__floats2half2_rn(va.z, va.w));
            u.z = h2u(__floats2half2_rn(vb.x, vb.y));
            u.w = h2u(__floats2half2_rn(vb.z, vb.w));
            *(uint4*)(Bs32 + row * (LDA / 2) + g * 4) = u;
        }
        __syncthreads();
#pragma unroll
        for (int ks = 0; ks < TKC / 16; ++ks) {
            uint32_t bf[4][2];
#pragma unroll
            for (int nt = 0; nt < 4; ++nt) {
                int rowB = (warpN * 32 + nt * 8 + r) * (LDA / 2) + ks * 8 + q;
                bf[nt][0] = Bs32[rowB];
                bf[nt][1] = Bs32[rowB + 4];
            }
#pragma unroll
            for (int mt = 0; mt < 2; ++mt) {
                int rowA0 = (warpM * 32 + mt * 16 + r) * (LDA / 2) + ks * 8 + q;
                int rowA1 = rowA0 + 8 * (LDA / 2);
                uint32_t a0 = As32[rowA0];
                uint32_t a1 = As32[rowA1];
                uint32_t a2 = As32[rowA0 + 4];
                uint32_t a3 = As32[rowA1 + 4];
#pragma unroll
                for (int nt = 0; nt < 4; ++nt)
                    mma16816(acc[mt][nt], a0, a1, a2, a3, bf[nt][0], bf[nt][1]);
            }
        }
        __syncthreads();
    }

    // ---- epilogue: relu+bias -> Hs (fp16, reuses A region), then GEMM2 ----
    __half* Hs = (__half*)(sm + SMO_A);   // stride LDA
#pragma unroll
    for (int mt = 0; mt < 2; ++mt) {
        int r0 = warpM * 32 + mt * 16 + r;
#pragma unroll
        for (int nt = 0; nt < 4; ++nt) {
            int col = warpN * 32 + nt * 8 + q * 2;
            float bb0 = b1[col], bb1 = b1[col + 1];
            float* a = acc[mt][nt];
            __half2 lo = __floats2half2_rn(fmaxf(a[0] + bb0, 0.f), fmaxf(a[1] + bb1, 0.f));
            __half2 hi = __floats2half2_rn(fmaxf(a[2] + bb0, 0.f), fmaxf(a[3] + bb1, 0.f));
            *(__half2*)(Hs + (size_t)r0 * LDA + col)       = lo;
            *(__half2*)(Hs + (size_t)(r0 + 8) * LDA + col) = hi;
        }
    }
    __syncthreads();

    // GEMM2: 256 threads -> (class = t&15, node-group = t>>4 of 8 nodes)
    int cls = t & 15, grp = t >> 4;
    float bc = b2[cls];
#pragma unroll
    for (int i = 0; i < 8; ++i) {
        int row = grp * 8 + i;
        int gn = nodeBase + row;
        float a = bc;
        const __half2* hr = (const __half2*)(Hs + (size_t)row * LDA);
#pragma unroll
        for (int k = 0; k < 32; ++k) {
            float2 f = __half22float2(hr[k]);
            a = fmaf(f.x, W2s[cls * LDW2 + 2 * k], a);
            a = fmaf(f.y, W2s[cls * LDW2 + 2 * k + 1], a);
        }
        if (gn < n) g_h0h[(size_t)gn * NCLS + cls] = __float2half_rn(a);
    }
}

// ---------------- APPNP step: fp16 h, 8 lanes/node, half2 gathers ------------
__global__ __launch_bounds__(256) void k_prop(int srcSel, int dstSel, int n) {
    int t = blockIdx.x * 256 + threadIdx.x;
    int node = t >> 3, lane = t & 7;
    bool valid = node < n;
    if (!valid) node = n - 1;
    const __half2* __restrict__ hin = (const __half2*)(
        (srcSel == 0) ? g_h0h : ((srcSel == 1) ? g_bufA : g_bufB));
    __half2* __restrict__ hout = (__half2*)((dstSel == 1) ? g_bufA : g_bufB);

    unsigned m8 = 0xFFu << (threadIdx.x & 24);
    int start = g_ptr[node], end = g_ptr[node + 1];
    float a0 = 0.f, a1 = 0.f;
    for (int base = start; base < end; base += 8) {
        int e = base + lane;
        int2 p = make_int2(-1, 0);
        if (e < end) p = __ldg(&g_edge[e]);
#pragma unroll
        for (int j = 0; j < 8; ++j) {
            int sj = __shfl_sync(m8, p.x, j, 8);
            int wb = __shfl_sync(m8, p.y, j, 8);
            if (sj >= 0) {
                float w = __int_as_float(wb);
                float2 f = __half22float2(__ldg(hin + (size_t)sj * 8 + lane));
                a0 = fmaf(w, f.x, a0);
                a1 = fmaf(w, f.y, a1);
            }
        }
    }
    float dv = g_dis[node];
    float d2 = dv * dv;
    float2 own = __half22float2(hin[(size_t)node * 8 + lane]);
    a0 = fmaf(d2, own.x, a0);
    a1 = fmaf(d2, own.y, a1);
    float2 z = __half22float2(((const __half2*)g_h0h)[(size_t)node * 8 + lane]);
    float r0 = 0.9f * a0 + 0.1f * z.x;
    float r1 = 0.9f * a1 + 0.1f * z.y;
    if (valid) hout[(size_t)node * 8 + lane] = __floats2half2_rn(r0, r1);
}

// ---------------- log-softmax (thread per node) ----------------
__global__ void k_lsm(float* __restrict__ out, int n) {
    int nd = blockIdx.x * blockDim.x + threadIdx.x;
    if (nd >= n) return;
    const __half2* hb = (const __half2*)g_bufB + (size_t)nd * 8;
    float v[16];
#pragma unroll
    for (int i = 0; i < 8; ++i) {
        float2 f = __half22float2(hb[i]);
        v[2 * i] = f.x;
        v[2 * i + 1] = f.y;
    }
    float m = v[0];
#pragma unroll
    for (int i = 1; i < 16; ++i) m = fmaxf(m, v[i]);
    float s = 0.f;
#pragma unroll
    for (int i = 0; i < 16; ++i) s += expf(v[i] - m);
    float ls = m + logf(s);
    float* o = out + (size_t)nd * 16;
#pragma unroll
    for (int i = 0; i < 16; i += 4) {
        float4 qv = make_float4(v[i] - ls, v[i + 1] - ls, v[i + 2] - ls, v[i + 3] - ls);
        *(float4*)(o + i) = qv;
    }
}

// ---------------- launch ----------------
extern "C" void kernel_launch(void* const* d_in, const int* in_sizes, int n_in,
                              void* d_out, int out_size) {
    const float* x  = (const float*)d_in[0];
    const float* W1 = (const float*)d_in[1];
    const float* b1 = (const float*)d_in[2];
    const float* W2 = (const float*)d_in[3];
    const float* b2 = (const float*)d_in[4];
    const void*  ei = d_in[5];
    float* out = (float*)d_out;

    int N = in_sizes[0] / NFEAT;
    int E = in_sizes[5] / 2;
    int sblocks = (N + SCAN_ELEMS - 1) / SCAN_ELEMS;

    k_detect<<<1, 256>>>((const int*)ei, E);
    k_init<<<(N + 255) / 256, 256>>>(N);
    k_count<<<(E + 255) / 256, 256>>>(ei, E);
    k_dis<<<(N + 255) / 256, 256>>>(N);
    k_scan1<<<sblocks, SCAN_T>>>(N);
    k_scan2<<<1, 32>>>(sblocks, N);
    k_scan3<<<sblocks, SCAN_T>>>(N);
    k_fill<<<(E + 255) / 256, 256>>>(ei, E);

    k_gemm<<<(N + TM - 1) / TM, 256>>>(x, W1, b1, W2, b2, N);

    int grid = (N * 8 + 255) / 256;
    int src = 0;
    for (int step = 1; step <= 10; ++step) {
        int dst = (step & 1) ? 1 : 2;
        k_prop<<<grid, 256>>>(src, dst, N);
        src = dst;
    }
    k_lsm<<<(N + 255) / 256, 256>>>(out, N);
}